// round 1
// baseline (speedup 1.0000x reference)
#include <cuda_runtime.h>

#define S_    2048
#define B_    2
#define D_    1024
#define H_    16
#define DH_   64
#define BH_   32          // B_*H_
#define ROWS_ 4096        // S_*B_
#define QLD_  3072        // row stride of g_qkv
#define ARS_  6144        // seq-row stride inside g_qkv = B_*QLD_

// ---- scratch (static device globals; no allocation) ----
__device__ float g_qkv[ROWS_ * 3072];                 // [s*B+b][3*H*DH]  (q|k|v)
__device__ float g_r  [S_ * D_];                      // [t][h*64+d]
__device__ float g_bd [(size_t)BH_ * S_ * S_];        // raw (q+v)·r  per (b,h)
__device__ float g_sc [(size_t)BH_ * S_ * S_];        // scores -> probs (in place)
__device__ float g_att[ROWS_ * D_];                   // attn_vec
__device__ float g_y  [ROWS_ * D_];                   // x + attn_out

// ============================================================
// Generic 128x128x8 SGEMM (row-major NN). MODE selects output:
//  0: g_qkv   1: g_r   2: g_y (A = g_att, adds residual Xres)
// ============================================================
template <int MODE>
__global__ __launch_bounds__(256) void sgemm_nn_k(const float* __restrict__ A,
                                                  const float* __restrict__ Bw,
                                                  const float* __restrict__ Xres,
                                                  int M, int N, int K)
{
    __shared__ float As[8][128];
    __shared__ float Bs[8][128];
    const float* Ap = (MODE == 2) ? g_att : A;
    float* C = (MODE == 0) ? g_qkv : (MODE == 1) ? g_r : g_y;

    int tid = threadIdx.x;
    int tx = tid & 15, ty = tid >> 4;
    size_t m0 = (size_t)blockIdx.y * 128;
    size_t n0 = (size_t)blockIdx.x * 128;
    int arow = tid >> 1, acol = (tid & 1) << 2;
    int brow = tid >> 5, bcol = (tid & 31) << 2;

    float acc[8][8] = {};
    for (int kk = 0; kk < K; kk += 8) {
        float4 a4 = *(const float4*)(Ap + (m0 + arow) * K + kk + acol);
        As[acol + 0][arow] = a4.x; As[acol + 1][arow] = a4.y;
        As[acol + 2][arow] = a4.z; As[acol + 3][arow] = a4.w;
        *(float4*)&Bs[brow][bcol] =
            *(const float4*)(Bw + (size_t)(kk + brow) * N + n0 + bcol);
        __syncthreads();
#pragma unroll
        for (int k = 0; k < 8; ++k) {
            float4 a0 = *(const float4*)&As[k][ty * 8];
            float4 a1 = *(const float4*)&As[k][ty * 8 + 4];
            float4 b0 = *(const float4*)&Bs[k][tx * 8];
            float4 b1 = *(const float4*)&Bs[k][tx * 8 + 4];
            float a[8] = {a0.x, a0.y, a0.z, a0.w, a1.x, a1.y, a1.z, a1.w};
            float b[8] = {b0.x, b0.y, b0.z, b0.w, b1.x, b1.y, b1.z, b1.w};
#pragma unroll
            for (int i = 0; i < 8; i++)
#pragma unroll
                for (int j = 0; j < 8; j++)
                    acc[i][j] = fmaf(a[i], b[j], acc[i][j]);
        }
        __syncthreads();
    }
#pragma unroll
    for (int i = 0; i < 8; i++) {
        size_t m = m0 + ty * 8 + i;
#pragma unroll
        for (int j = 0; j < 8; j++) {
            size_t n = n0 + tx * 8 + j;
            float v = acc[i][j];
            if (MODE == 2) v += Xres[m * N + n];
            C[m * N + n] = v;
        }
    }
}

// ============================================================
// Batched per-(b,h) NT GEMMs over K=64, tile 128x128x8.
// MODE 0: Draw[i,t] = (q_i + pos_bias_v) . r_t            -> g_bd
// MODE 1: AC[i,j]   = (q_i + pos_bias_u) . k_j  then add
//         rel-shifted Draw, scale, write                  -> g_sc
// ============================================================
template <int MODE>
__global__ __launch_bounds__(256) void score_k(const float* __restrict__ bias_all)
{
    __shared__ float As[8][128];
    __shared__ float Bs[8][128];
    int bh = blockIdx.z, b = bh >> 4, h = bh & 15;
    const float* Aq = g_qkv + b * QLD_ + h * 64;     // q rows (stride ARS_)
    const float* Bp = (MODE == 0) ? (g_r + h * 64)
                                  : (g_qkv + b * QLD_ + 1024 + h * 64);
    size_t brs = (MODE == 0) ? (size_t)D_ : (size_t)ARS_;
    const float* bias = bias_all + h * 64;

    int tid = threadIdx.x;
    int tx = tid & 15, ty = tid >> 4;
    int i0 = blockIdx.y * 128;
    int j0 = blockIdx.x * 128;
    int arow = tid >> 1, acol = (tid & 1) << 2;

    float acc[8][8] = {};
    for (int kk = 0; kk < 64; kk += 8) {
        float4 a4 = *(const float4*)(Aq + (size_t)(i0 + arow) * ARS_ + kk + acol);
        float4 u4 = *(const float4*)(bias + kk + acol);
        As[acol + 0][arow] = a4.x + u4.x; As[acol + 1][arow] = a4.y + u4.y;
        As[acol + 2][arow] = a4.z + u4.z; As[acol + 3][arow] = a4.w + u4.w;
        float4 b4 = *(const float4*)(Bp + (size_t)(j0 + arow) * brs + kk + acol);
        Bs[acol + 0][arow] = b4.x; Bs[acol + 1][arow] = b4.y;
        Bs[acol + 2][arow] = b4.z; Bs[acol + 3][arow] = b4.w;
        __syncthreads();
#pragma unroll
        for (int k = 0; k < 8; ++k) {
            float4 a0 = *(const float4*)&As[k][ty * 8];
            float4 a1 = *(const float4*)&As[k][ty * 8 + 4];
            float4 b0 = *(const float4*)&Bs[k][tx * 8];
            float4 b1 = *(const float4*)&Bs[k][tx * 8 + 4];
            float a[8] = {a0.x, a0.y, a0.z, a0.w, a1.x, a1.y, a1.z, a1.w};
            float bb[8] = {b0.x, b0.y, b0.z, b0.w, b1.x, b1.y, b1.z, b1.w};
#pragma unroll
            for (int i = 0; i < 8; i++)
#pragma unroll
                for (int j = 0; j < 8; j++)
                    acc[i][j] = fmaf(a[i], bb[j], acc[i][j]);
        }
        __syncthreads();
    }

    size_t base = (size_t)bh * S_ * S_;
    if (MODE == 0) {
#pragma unroll
        for (int i = 0; i < 8; i++) {
            int ii = i0 + ty * 8 + i;
#pragma unroll
            for (int j = 0; j < 8; j++)
                g_bd[base + (size_t)ii * S_ + (j0 + tx * 8 + j)] = acc[i][j];
        }
    } else {
        const float* bd = g_bd + base;
#pragma unroll
        for (int i = 0; i < 8; i++) {
            int ii = i0 + ty * 8 + i;
#pragma unroll
            for (int j = 0; j < 8; j++) {
                int jj = j0 + tx * 8 + j;
                float bdv;
                if (jj <= ii)          bdv = bd[(size_t)ii * S_ + (S_ - 1 + jj - ii)];
                else if (jj == ii + 1) bdv = 0.f;
                else                   bdv = bd[(size_t)(ii + 1) * S_ + (jj - ii - 2)];
                g_sc[base + (size_t)ii * S_ + jj] = 0.125f * (acc[i][j] + bdv);
            }
        }
    }
}

// ============================================================
// Row softmax over j (2048) for every (b,h,i) row. In place.
// ============================================================
__global__ __launch_bounds__(256) void softmax_k()
{
    __shared__ float red[8];
    float* p = g_sc + (size_t)blockIdx.x * S_;
    int tid = threadIdx.x;
    float v[8];
    float m = -1e30f;
#pragma unroll
    for (int l = 0; l < 8; l++) { v[l] = p[tid + l * 256]; m = fmaxf(m, v[l]); }
#pragma unroll
    for (int o = 16; o; o >>= 1) m = fmaxf(m, __shfl_xor_sync(0xffffffffu, m, o));
    if ((tid & 31) == 0) red[tid >> 5] = m;
    __syncthreads();
    float mm = red[0];
#pragma unroll
    for (int w = 1; w < 8; w++) mm = fmaxf(mm, red[w]);
    __syncthreads();
    float s = 0.f;
#pragma unroll
    for (int l = 0; l < 8; l++) { v[l] = __expf(v[l] - mm); s += v[l]; }
#pragma unroll
    for (int o = 16; o; o >>= 1) s += __shfl_xor_sync(0xffffffffu, s, o);
    if ((tid & 31) == 0) red[tid >> 5] = s;
    __syncthreads();
    float tot = 0.f;
#pragma unroll
    for (int w = 0; w < 8; w++) tot += red[w];
    float inv = 1.f / tot;
#pragma unroll
    for (int l = 0; l < 8; l++) p[tid + l * 256] = v[l] * inv;
}

// ============================================================
// PV: attn_vec[i, (b,h,d)] = sum_j P[i,j] * v[j,d]. Tile 128x64x16.
// ============================================================
__global__ __launch_bounds__(256) void pv_k()
{
    __shared__ float As[16][128];
    __shared__ float Bs[16][64];
    int bh = blockIdx.y, b = bh >> 4, h = bh & 15;
    const float* P = g_sc + (size_t)bh * S_ * S_;
    const float* V = g_qkv + b * QLD_ + 2048 + h * 64;

    int tid = threadIdx.x;
    int tx = tid & 15, ty = tid >> 4;
    int i0 = blockIdx.x * 128;
    int br = tid >> 4, bc = (tid & 15) << 2;

    float acc[8][4] = {};
    for (int kk = 0; kk < S_; kk += 16) {
#pragma unroll
        for (int l = 0; l < 2; l++) {
            int idx = tid + l * 256;
            int r = idx >> 2, c = (idx & 3) << 2;
            float4 a4 = *(const float4*)(P + (size_t)(i0 + r) * S_ + kk + c);
            As[c + 0][r] = a4.x; As[c + 1][r] = a4.y;
            As[c + 2][r] = a4.z; As[c + 3][r] = a4.w;
        }
        *(float4*)&Bs[br][bc] = *(const float4*)(V + (size_t)(kk + br) * ARS_ + bc);
        __syncthreads();
#pragma unroll
        for (int k = 0; k < 16; k++) {
            float4 a0 = *(const float4*)&As[k][ty * 8];
            float4 a1 = *(const float4*)&As[k][ty * 8 + 4];
            float4 b0 = *(const float4*)&Bs[k][tx * 4];
            float a[8] = {a0.x, a0.y, a0.z, a0.w, a1.x, a1.y, a1.z, a1.w};
            float bb[4] = {b0.x, b0.y, b0.z, b0.w};
#pragma unroll
            for (int i = 0; i < 8; i++)
#pragma unroll
                for (int j = 0; j < 4; j++)
                    acc[i][j] = fmaf(a[i], bb[j], acc[i][j]);
        }
        __syncthreads();
    }
#pragma unroll
    for (int i = 0; i < 8; i++) {
        int si = i0 + ty * 8 + i;
#pragma unroll
        for (int j = 0; j < 4; j++)
            g_att[((size_t)si * B_ + b) * D_ + h * 64 + tx * 4 + j] = acc[i][j];
    }
}

// ============================================================
// LayerNorm over D=1024 per row; writes final output.
// ============================================================
__global__ __launch_bounds__(256) void ln_k(const float* __restrict__ gamma,
                                            const float* __restrict__ beta,
                                            float* __restrict__ out)
{
    __shared__ float reds[8], redq[8];
    const float* y = g_y + (size_t)blockIdx.x * D_;
    int tid = threadIdx.x;
    float v[4];
    float s = 0.f, q = 0.f;
#pragma unroll
    for (int l = 0; l < 4; l++) {
        v[l] = y[tid + l * 256];
        s += v[l];
        q += v[l] * v[l];
    }
#pragma unroll
    for (int o = 16; o; o >>= 1) {
        s += __shfl_xor_sync(0xffffffffu, s, o);
        q += __shfl_xor_sync(0xffffffffu, q, o);
    }
    if ((tid & 31) == 0) { reds[tid >> 5] = s; redq[tid >> 5] = q; }
    __syncthreads();
    float ts = 0.f, tq = 0.f;
#pragma unroll
    for (int w = 0; w < 8; w++) { ts += reds[w]; tq += redq[w]; }
    float mu = ts * (1.f / 1024.f);
    float var = tq * (1.f / 1024.f) - mu * mu;
    float inv = rsqrtf(var + 1e-5f);
    float* o = out + (size_t)blockIdx.x * D_;
#pragma unroll
    for (int l = 0; l < 4; l++) {
        int c = tid + l * 256;
        o[c] = (v[l] - mu) * inv * gamma[c] + beta[c];
    }
}

// ============================================================
extern "C" void kernel_launch(void* const* d_in, const int* in_sizes, int n_in,
                              void* d_out, int out_size)
{
    const float* x    = (const float*)d_in[0];
    const float* pe   = (const float*)d_in[1];
    const float* pbu  = (const float*)d_in[2];
    const float* pbv  = (const float*)d_in[3];
    const float* Wqkv = (const float*)d_in[4];
    const float* Wrel = (const float*)d_in[5];
    const float* Wo   = (const float*)d_in[6];
    const float* gam  = (const float*)d_in[7];
    const float* bet  = (const float*)d_in[8];
    float* out = (float*)d_out;

    // 1) qkv = x @ W_qkv                [4096,1024]x[1024,3072]
    sgemm_nn_k<0><<<dim3(24, 32), 256>>>(x, Wqkv, nullptr, 4096, 3072, 1024);
    // 2) r = pos_emb @ W_relemb         [2048,1024]x[1024,1024]
    sgemm_nn_k<1><<<dim3(8, 16), 256>>>(pe, Wrel, nullptr, 2048, 1024, 1024);
    // 3) Draw = (q + v_bias) @ r^T  per (b,h)
    score_k<0><<<dim3(16, 16, 32), 256>>>(pbv);
    // 4) score = scale * ((q + u_bias) @ k^T + rel_shift(Draw))
    score_k<1><<<dim3(16, 16, 32), 256>>>(pbu);
    // 5) softmax over j
    softmax_k<<<BH_ * S_, 256>>>();
    // 6) attn_vec = P @ V per (b,h)
    pv_k<<<dim3(16, 32), 256>>>();
    // 7) y = x + attn_vec @ W_o
    sgemm_nn_k<2><<<dim3(8, 32), 256>>>(nullptr, Wo, x, 4096, 1024, 1024);
    // 8) layernorm -> out
    ln_k<<<4096, 256>>>(gam, bet, out);
}